// round 1
// baseline (speedup 1.0000x reference)
#include <cuda_runtime.h>
#include <math.h>

#define HH 384
#define WW 384
#define HW (HH*WW)          // 147456
#define SUMN 128
#define BB 16
#define LL 8
#define CHUNKS 144          // HW / (256 threads * 4 floats) = 144
#define NEGV -1000000000.0f

// ---- scratch (static device globals; no runtime allocation allowed) ----
__device__ float g_conf[(size_t)SUMN * HW];   // 75.5 MB sigmoid-max buffer
__device__ float g_sum_conf[SUMN];
__device__ float g_sum_dem[BB];
__device__ float g_sum_ovl[SUMN];

__device__ __forceinline__ float sigf(float x) {
    return 1.0f / (1.0f + __expf(-x));
}

// block reduce over 256 threads; result valid in thread 0
__device__ __forceinline__ float blockReduce256(float v, float* sh) {
    #pragma unroll
    for (int o = 16; o > 0; o >>= 1) v += __shfl_xor_sync(0xffffffffu, v, o);
    if ((threadIdx.x & 31) == 0) sh[threadIdx.x >> 5] = v;
    __syncthreads();
    if (threadIdx.x < 8) {
        v = sh[threadIdx.x];
        #pragma unroll
        for (int o = 4; o > 0; o >>= 1) v += __shfl_xor_sync(0xffu, v, o);
    }
    return v;
}

__global__ void k_init() {
    int t = threadIdx.x;
    if (t < SUMN) { g_sum_conf[t] = 0.0f; g_sum_ovl[t] = 0.0f; }
    if (t < BB)   { g_sum_dem[t] = 0.0f; }
}

// conf = max_c sigmoid(psm); accumulate per-image sum; accumulate demand for l==0 images
__global__ void __launch_bounds__(256) k_conf(const float* __restrict__ psm,
                                              const float* __restrict__ req) {
    __shared__ float sh[8];
    int n     = blockIdx.x / CHUNKS;
    int chunk = blockIdx.x % CHUNKS;
    int base  = chunk * 1024 + threadIdx.x * 4;

    const float4 a4 = *(const float4*)(psm + (size_t)n * 2 * HW + base);
    const float4 b4 = *(const float4*)(psm + (size_t)n * 2 * HW + HW + base);
    float4 c;
    c.x = fmaxf(sigf(a4.x), sigf(b4.x));
    c.y = fmaxf(sigf(a4.y), sigf(b4.y));
    c.z = fmaxf(sigf(a4.z), sigf(b4.z));
    c.w = fmaxf(sigf(a4.w), sigf(b4.w));
    *(float4*)(g_conf + (size_t)n * HW + base) = c;

    float s = (c.x + c.y) + (c.z + c.w);
    float r = blockReduce256(s, sh);
    if (threadIdx.x == 0) atomicAdd(&g_sum_conf[n], r);

    if ((n & (LL - 1)) == 0) {  // this image's req_mask defines demand for batch n/LL
        __syncthreads();        // protect sh reuse
        const float4 d4 = *(const float4*)(req + (size_t)n * HW + base);
        float sd = (d4.x + d4.y) + (d4.z + d4.w);
        float rd = blockReduce256(sd, sh);
        if (threadIdx.x == 0) atomicAdd(&g_sum_dem[n >> 3], rd);
    }
}

__device__ __forceinline__ float tap(const float* __restrict__ img, int y, int x) {
    if ((unsigned)x < WW && (unsigned)y < HH) return __ldg(img + y * WW + x);
    return 0.0f;
}

// bilinear warp of conf[b,l] by Aij[b,l]=norm_affine[b,0,l], dot with Di[b], reduce
__global__ void __launch_bounds__(256) k_warp(const float* __restrict__ na,
                                              const float* __restrict__ req) {
    __shared__ float sh[8];
    int pair  = blockIdx.x / CHUNKS;
    int chunk = blockIdx.x % CHUNKS;
    int b = pair >> 3, l = pair & 7;

    const float* A = na + (size_t)((b * LL + 0) * LL + l) * 6;
    float A00 = A[0], A01 = A[1], A02 = A[2];
    float A10 = A[3], A11 = A[4], A12 = A[5];

    const float* __restrict__ conf = g_conf + (size_t)pair * HW;
    const float* __restrict__ Di   = req + (size_t)(b * LL) * HW;

    int p0 = chunk * 1024 + threadIdx.x * 4;
    const float4 d4 = *(const float4*)(Di + p0);
    float dv[4] = {d4.x, d4.y, d4.z, d4.w};

    const float step = 2.0f / (WW - 1);
    float acc = 0.0f;
    #pragma unroll
    for (int k = 0; k < 4; k++) {
        int p = p0 + k;
        int y = p / WW, x = p - y * WW;
        float gx = fmaf((float)x, step, -1.0f);
        float gy = fmaf((float)y, step, -1.0f);
        float sx = A00 * gx + A01 * gy + A02;
        float sy = A10 * gx + A11 * gy + A12;
        float px = (sx + 1.0f) * ((WW - 1) * 0.5f);
        float py = (sy + 1.0f) * ((HH - 1) * 0.5f);
        float x0f = floorf(px), y0f = floorf(py);
        float wx = px - x0f, wy = py - y0f;
        int x0 = (int)x0f, y0 = (int)y0f;
        float v00 = tap(conf, y0,     x0);
        float v01 = tap(conf, y0,     x0 + 1);
        float v10 = tap(conf, y0 + 1, x0);
        float v11 = tap(conf, y0 + 1, x0 + 1);
        float top = v00 * (1.0f - wx) + v01 * wx;
        float bot = v10 * (1.0f - wx) + v11 * wx;
        float w   = top * (1.0f - wy) + bot * wy;
        acc += w * dv[k];
    }
    float r = blockReduce256(acc, sh);
    if (threadIdx.x == 0) atomicAdd(&g_sum_ovl[pair], r);
}

// full MLP head: 128 blocks (one per (b,l) row), 64 threads (one per hidden unit)
__global__ void __launch_bounds__(64) k_head(
    const float* __restrict__ na,
    const float* __restrict__ qW1, const float* __restrict__ qb1,
    const float* __restrict__ qW2, const float* __restrict__ qb2,
    const float* __restrict__ kW1, const float* __restrict__ kb1,
    const float* __restrict__ kW2, const float* __restrict__ kb2,
    const float* __restrict__ eW1, const float* __restrict__ eb1,
    const float* __restrict__ eW2, const float* __restrict__ eb2,
    float* __restrict__ out)
{
    __shared__ float s_feat[8], s_ego[8], s_h[64], s_qk[128], s_red[2];
    int row = blockIdx.x;
    int t = threadIdx.x;
    int b = row >> 3, l = row & 7;
    const float invHW = 1.0f / (float)HW;

    if (t == 0) {
        float mc  = g_sum_conf[row]      * invHW;
        float mc0 = g_sum_conf[b * LL]   * invHW;
        float dem = g_sum_dem[b]         * invHW;
        float ovl = g_sum_ovl[row]       * invHW;
        const float* A  = na + (size_t)((b * LL + 0) * LL + l) * 6;  // Aij
        float dx = A[2], dy = A[5];
        float dist = sqrtf(dx * dx + dy * dy);
        const float* Dl = na + (size_t)((b * LL + l) * LL + l) * 6;  // diag[b,l]
        const float* D0 = na + (size_t)((b * LL + 0) * LL + 0) * 6;  // diag[b,0]
        float yawl = atan2f(Dl[3], Dl[0]);
        float yaw0 = atan2f(D0[3], D0[0]);
        float d = yaw0 - yawl;
        float dyaw = atan2f(sinf(d), cosf(d));
        s_feat[0] = mc;   s_feat[1] = ovl;  s_feat[2] = dx;
        s_feat[3] = dy;   s_feat[4] = cosf(dyaw); s_feat[5] = sinf(dyaw);
        s_feat[6] = dist; s_feat[7] = dem;
        s_ego[0] = mc0; s_ego[1] = dem; s_ego[2] = 0.0f; s_ego[3] = 0.0f;
        s_ego[4] = 1.0f; s_ego[5] = 0.0f; s_ego[6] = 0.0f; s_ego[7] = dem;
    }
    __syncthreads();

    // q = mlp2(ego)
    float h = qb1[t];
    #pragma unroll
    for (int i = 0; i < 8; i++) h = fmaf(s_ego[i], qW1[i * 64 + t], h);
    s_h[t] = fmaxf(h, 0.0f);
    __syncthreads();
    float qv = qb2[t];
    #pragma unroll 8
    for (int i = 0; i < 64; i++) qv = fmaf(s_h[i], qW2[i * 64 + t], qv);
    s_qk[t] = qv;
    __syncthreads();

    // k = mlp2(feat)
    h = kb1[t];
    #pragma unroll
    for (int i = 0; i < 8; i++) h = fmaf(s_feat[i], kW1[i * 64 + t], h);
    s_h[t] = fmaxf(h, 0.0f);
    __syncthreads();
    float kv = kb2[t];
    #pragma unroll 8
    for (int i = 0; i < 64; i++) kv = fmaf(s_h[i], kW2[i * 64 + t], kv);
    s_qk[64 + t] = kv;
    __syncthreads();

    // e = mlp2(concat(q,k)) -> scalar
    float e = eb1[t];
    #pragma unroll 8
    for (int i = 0; i < 128; i++) e = fmaf(s_qk[i], eW1[i * 64 + t], e);
    e = fmaxf(e, 0.0f) * eW2[t];
    #pragma unroll
    for (int o = 16; o > 0; o >>= 1) e += __shfl_xor_sync(0xffffffffu, e, o);
    if ((t & 31) == 0) s_red[t >> 5] = e;
    __syncthreads();
    if (t == 0) {
        float logit = s_red[0] + s_red[1] + eb2[0];
        if (l == 0) logit = NEGV;
        float sg = 1.0f / (1.0f + expf(-logit));
        out[row] = fminf(fmaxf(sg, 0.0f), 1.0f);
    }
}

extern "C" void kernel_launch(void* const* d_in, const int* in_sizes, int n_in,
                              void* d_out, int out_size) {
    const float* psm = (const float*)d_in[0];
    const float* req = (const float*)d_in[1];
    const float* na  = (const float*)d_in[2];
    // d_in[3] = record_len (unused; always full)
    const float* qW1 = (const float*)d_in[4];
    const float* qb1 = (const float*)d_in[5];
    const float* qW2 = (const float*)d_in[6];
    const float* qb2 = (const float*)d_in[7];
    const float* kW1 = (const float*)d_in[8];
    const float* kb1 = (const float*)d_in[9];
    const float* kW2 = (const float*)d_in[10];
    const float* kb2 = (const float*)d_in[11];
    const float* eW1 = (const float*)d_in[12];
    const float* eb1 = (const float*)d_in[13];
    const float* eW2 = (const float*)d_in[14];
    const float* eb2 = (const float*)d_in[15];
    float* out = (float*)d_out;

    k_init<<<1, 128>>>();
    k_conf<<<SUMN * CHUNKS, 256>>>(psm, req);
    k_warp<<<SUMN * CHUNKS, 256>>>(na, req);
    k_head<<<SUMN, 64>>>(na, qW1, qb1, qW2, qb2, kW1, kb1, kW2, kb2,
                         eW1, eb1, eW2, eb2, out);
}

// round 3
// speedup vs baseline: 1.0595x; 1.0595x over previous
#include <cuda_runtime.h>
#include <cuda_fp16.h>
#include <math.h>

#define HH 384
#define WW 384
#define HW (HH*WW)          // 147456
#define SUMN 128
#define BB 16
#define LL 8
#define CHUNKS 144          // HW / (256 threads * 4 floats)
#define NEGV -1000000000.0f

// ---- scratch (static device globals; no runtime allocation allowed) ----
__device__ __half g_conf16[(size_t)SUMN * HW];   // 37.7 MB fp16 conf buffer
__device__ float  g_pconf[SUMN * CHUNKS];        // per-block partial conf sums
__device__ float  g_pdem[BB * CHUNKS];           // per-block partial demand sums
__device__ float  g_povl[SUMN * CHUNKS];         // per-block partial overlap sums

__device__ __forceinline__ float sigf(float x) {
    return 1.0f / (1.0f + __expf(-x));
}

// block reduce over 256 threads; full sum valid in thread 0
__device__ __forceinline__ float blockReduce256(float v, float* sh) {
    #pragma unroll
    for (int o = 16; o > 0; o >>= 1) v += __shfl_xor_sync(0xffffffffu, v, o);
    if ((threadIdx.x & 31) == 0) sh[threadIdx.x >> 5] = v;
    __syncthreads();
    if (threadIdx.x < 8) {
        v = sh[threadIdx.x];
        #pragma unroll
        for (int o = 4; o > 0; o >>= 1) v += __shfl_xor_sync(0xffu, v, o);
    }
    return v;
}

// conf = sigmoid(max_c psm)  [sigmoid is monotonic];  partial per-image sums; demand for l==0
__global__ void __launch_bounds__(256) k_conf(const float* __restrict__ psm,
                                              const float* __restrict__ req) {
    __shared__ float sh[8];
    int n     = blockIdx.x / CHUNKS;
    int chunk = blockIdx.x % CHUNKS;
    int base  = chunk * 1024 + threadIdx.x * 4;

    const float4 a4 = *(const float4*)(psm + (size_t)n * 2 * HW + base);
    const float4 b4 = *(const float4*)(psm + (size_t)n * 2 * HW + HW + base);
    float4 c;
    c.x = sigf(fmaxf(a4.x, b4.x));
    c.y = sigf(fmaxf(a4.y, b4.y));
    c.z = sigf(fmaxf(a4.z, b4.z));
    c.w = sigf(fmaxf(a4.w, b4.w));

    __half2 h01 = __floats2half2_rn(c.x, c.y);
    __half2 h23 = __floats2half2_rn(c.z, c.w);
    uint2 u;
    u.x = *reinterpret_cast<unsigned int*>(&h01);
    u.y = *reinterpret_cast<unsigned int*>(&h23);
    *reinterpret_cast<uint2*>(g_conf16 + (size_t)n * HW + base) = u;

    float s = (c.x + c.y) + (c.z + c.w);
    float r = blockReduce256(s, sh);
    if (threadIdx.x == 0) g_pconf[n * CHUNKS + chunk] = r;

    if ((n & (LL - 1)) == 0) {   // demand for batch n/8 comes from this image's req_mask
        __syncthreads();         // protect sh reuse
        const float4 d4 = *(const float4*)(req + (size_t)n * HW + base);
        float sd = (d4.x + d4.y) + (d4.z + d4.w);
        float rd = blockReduce256(sd, sh);
        if (threadIdx.x == 0) g_pdem[(n >> 3) * CHUNKS + chunk] = rd;
    }
}

__device__ __forceinline__ float tap16(const __half* __restrict__ img, int y, int x) {
    if ((unsigned)x < WW && (unsigned)y < HH) return __half2float(__ldg(img + y * WW + x));
    return 0.0f;
}

// bilinear warp of conf[b,l] by Aij = norm_affine[b,0,l], dot with Di[b], partial reduce
__global__ void __launch_bounds__(256) k_warp(const float* __restrict__ na,
                                              const float* __restrict__ req) {
    __shared__ float sh[8];
    int pair  = blockIdx.x / CHUNKS;
    int chunk = blockIdx.x % CHUNKS;
    int b = pair >> 3;

    const float* A = na + (size_t)((b * LL + 0) * LL + (pair & 7)) * 6;
    float A00 = A[0], A01 = A[1], A02 = A[2];
    float A10 = A[3], A11 = A[4], A12 = A[5];

    const __half* __restrict__ conf = g_conf16 + (size_t)pair * HW;
    const float*  __restrict__ Di   = req + (size_t)(b * LL) * HW;

    int p0 = chunk * 1024 + threadIdx.x * 4;
    int y  = p0 / WW;                 // 4 | WW -> all 4 px share this row
    int x0base = p0 - y * WW;
    const float4 d4 = *(const float4*)(Di + p0);
    float dv[4] = {d4.x, d4.y, d4.z, d4.w};

    const float step = 2.0f / (WW - 1);
    float gy = fmaf((float)y, step, -1.0f);
    float gx = fmaf((float)x0base, step, -1.0f);
    // row-constant terms
    float sx = fmaf(A01, gy, A02) + A00 * gx;
    float sy = fmaf(A11, gy, A12) + A10 * gx;
    float dsx = A00 * step, dsy = A10 * step;

    float acc = 0.0f;
    #pragma unroll
    for (int k = 0; k < 4; k++) {
        float px = (sx + 1.0f) * ((WW - 1) * 0.5f);
        float py = (sy + 1.0f) * ((HH - 1) * 0.5f);
        float x0f = floorf(px), y0f = floorf(py);
        float wx = px - x0f, wy = py - y0f;
        int xi = (int)x0f, yi = (int)y0f;
        float v00 = tap16(conf, yi,     xi);
        float v01 = tap16(conf, yi,     xi + 1);
        float v10 = tap16(conf, yi + 1, xi);
        float v11 = tap16(conf, yi + 1, xi + 1);
        float top = v00 + (v01 - v00) * wx;
        float bot = v10 + (v11 - v10) * wx;
        acc = fmaf((top + (bot - top) * wy), dv[k], acc);
        sx += dsx; sy += dsy;
    }
    float r = blockReduce256(acc, sh);
    if (threadIdx.x == 0) g_povl[pair * CHUNKS + chunk] = r;
}

// MLP head: 8 blocks x 1024 threads; 16 rows per block, 64 threads per row-group
__global__ void __launch_bounds__(1024) k_head(
    const float* __restrict__ na,
    const float* __restrict__ qW1, const float* __restrict__ qb1,
    const float* __restrict__ qW2, const float* __restrict__ qb2,
    const float* __restrict__ kW1, const float* __restrict__ kb1,
    const float* __restrict__ kW2, const float* __restrict__ kb2,
    const float* __restrict__ eW1, const float* __restrict__ eb1,
    const float* __restrict__ eW2, const float* __restrict__ eb2,
    float* __restrict__ out)
{
    __shared__ float s_qW1[512], s_kW1[512];
    __shared__ float s_qb1[64], s_qb2[64], s_kb1[64], s_kb2[64], s_eb1[64], s_eW2[64];
    __shared__ float s_h[16][64];
    __shared__ float s_qk[16][128];
    __shared__ float s_feat[16][8], s_ego[16][8];
    __shared__ float s_scr[16][8];

    int t = threadIdx.x;
    // stage small weights
    for (int i = t; i < 512; i += 1024) { s_qW1[i] = qW1[i]; s_kW1[i] = kW1[i]; }
    if (t < 64) {
        s_qb1[t] = qb1[t]; s_qb2[t] = qb2[t];
        s_kb1[t] = kb1[t]; s_kb2[t] = kb2[t];
        s_eb1[t] = eb1[t]; s_eW2[t] = eW2[t];
    }

    int g    = t >> 6;          // row group 0..15
    int lane = t & 63;
    int row  = blockIdx.x * 16 + g;
    int b = row >> 3, l = row & 7;
    const float invHW = 1.0f / (float)HW;

    // reduce partial sums (144 each) for this row
    float pc = 0.f, po = 0.f, pd = 0.f, pc0 = 0.f;
    for (int i = lane; i < CHUNKS; i += 64) {
        pc  += g_pconf[row * CHUNKS + i];
        po  += g_povl[row * CHUNKS + i];
        pd  += g_pdem[b * CHUNKS + i];
        pc0 += g_pconf[(b * LL) * CHUNKS + i];
    }
    #pragma unroll
    for (int o = 16; o > 0; o >>= 1) {
        pc  += __shfl_xor_sync(0xffffffffu, pc,  o);
        po  += __shfl_xor_sync(0xffffffffu, po,  o);
        pd  += __shfl_xor_sync(0xffffffffu, pd,  o);
        pc0 += __shfl_xor_sync(0xffffffffu, pc0, o);
    }
    if ((lane & 31) == 0) {
        float* scr = &s_scr[g][(lane >> 5) * 4];
        scr[0] = pc; scr[1] = po; scr[2] = pd; scr[3] = pc0;
    }
    __syncthreads();

    if (lane == 0) {
        float sc  = (s_scr[g][0] + s_scr[g][4]) * invHW;
        float so  = (s_scr[g][1] + s_scr[g][5]) * invHW;
        float sd  = (s_scr[g][2] + s_scr[g][6]) * invHW;
        float sc0 = (s_scr[g][3] + s_scr[g][7]) * invHW;
        const float* A  = na + (size_t)((b * LL + 0) * LL + l) * 6;   // Aij
        float dx = A[2], dy = A[5];
        float dist = sqrtf(dx * dx + dy * dy);
        const float* Dl = na + (size_t)((b * LL + l) * LL + l) * 6;   // diag[b,l]
        const float* D0 = na + (size_t)((b * LL + 0) * LL + 0) * 6;   // diag[b,0]
        float yawl = atan2f(Dl[3], Dl[0]);
        float yaw0 = atan2f(D0[3], D0[0]);
        float d = yaw0 - yawl;
        float dyaw = atan2f(sinf(d), cosf(d));
        s_feat[g][0] = sc;   s_feat[g][1] = so;          s_feat[g][2] = dx;
        s_feat[g][3] = dy;   s_feat[g][4] = cosf(dyaw);  s_feat[g][5] = sinf(dyaw);
        s_feat[g][6] = dist; s_feat[g][7] = sd;
        s_ego[g][0] = sc0; s_ego[g][1] = sd;  s_ego[g][2] = 0.0f; s_ego[g][3] = 0.0f;
        s_ego[g][4] = 1.0f; s_ego[g][5] = 0.0f; s_ego[g][6] = 0.0f; s_ego[g][7] = sd;
    }
    __syncthreads();

    // q = mlp2(ego)
    float h = s_qb1[lane];
    #pragma unroll
    for (int i = 0; i < 8; i++) h = fmaf(s_ego[g][i], s_qW1[i * 64 + lane], h);
    s_h[g][lane] = fmaxf(h, 0.0f);
    __syncthreads();
    float qv = s_qb2[lane];
    #pragma unroll 8
    for (int i = 0; i < 64; i++) qv = fmaf(s_h[g][i], __ldg(qW2 + i * 64 + lane), qv);
    s_qk[g][lane] = qv;
    __syncthreads();

    // k = mlp2(feat)
    h = s_kb1[lane];
    #pragma unroll
    for (int i = 0; i < 8; i++) h = fmaf(s_feat[g][i], s_kW1[i * 64 + lane], h);
    s_h[g][lane] = fmaxf(h, 0.0f);
    __syncthreads();
    float kv = s_kb2[lane];
    #pragma unroll 8
    for (int i = 0; i < 64; i++) kv = fmaf(s_h[g][i], __ldg(kW2 + i * 64 + lane), kv);
    s_qk[g][64 + lane] = kv;
    __syncthreads();

    // e = mlp2(concat(q,k)) -> scalar
    float e = s_eb1[lane];
    #pragma unroll 8
    for (int i = 0; i < 128; i++) e = fmaf(s_qk[g][i], __ldg(eW1 + i * 64 + lane), e);
    e = fmaxf(e, 0.0f) * s_eW2[lane];
    #pragma unroll
    for (int o = 16; o > 0; o >>= 1) e += __shfl_xor_sync(0xffffffffu, e, o);
    if ((lane & 31) == 0) s_scr[g][lane >> 5] = e;
    __syncthreads();
    if (lane == 0) {
        float logit = s_scr[g][0] + s_scr[g][1] + eb2[0];
        if (l == 0) logit = NEGV;
        float sg = 1.0f / (1.0f + expf(-logit));
        out[row] = fminf(fmaxf(sg, 0.0f), 1.0f);
    }
}

extern "C" void kernel_launch(void* const* d_in, const int* in_sizes, int n_in,
                              void* d_out, int out_size) {
    const float* psm = (const float*)d_in[0];
    const float* req = (const float*)d_in[1];
    const float* na  = (const float*)d_in[2];
    // d_in[3] = record_len (unused; always full)
    const float* qW1 = (const float*)d_in[4];
    const float* qb1 = (const float*)d_in[5];
    const float* qW2 = (const float*)d_in[6];
    const float* qb2 = (const float*)d_in[7];
    const float* kW1 = (const float*)d_in[8];
    const float* kb1 = (const float*)d_in[9];
    const float* kW2 = (const float*)d_in[10];
    const float* kb2 = (const float*)d_in[11];
    const float* eW1 = (const float*)d_in[12];
    const float* eb1 = (const float*)d_in[13];
    const float* eW2 = (const float*)d_in[14];
    const float* eb2 = (const float*)d_in[15];
    float* out = (float*)d_out;

    k_conf<<<SUMN * CHUNKS, 256>>>(psm, req);
    k_warp<<<SUMN * CHUNKS, 256>>>(na, req);
    k_head<<<SUMN / 16, 1024>>>(na, qW1, qb1, qW2, qb2, kW1, kb1, kW2, kb2,
                                eW1, eb1, eW2, eb2, out);
}

// round 5
// speedup vs baseline: 1.1014x; 1.0395x over previous
#include <cuda_runtime.h>
#include <cuda_fp16.h>
#include <math.h>

#define HH 384
#define WW 384
#define HW (HH*WW)          // 147456
#define SUMN 128
#define BB 16
#define LL 8
#define CHUNKS 144          // HW / (256 threads * 4 floats)
#define NEGV -1000000000.0f

// ---- scratch (static device globals; no runtime allocation allowed) ----
__device__ __half g_conf16[(size_t)SUMN * HW];   // 37.7 MB fp16 conf buffer
__device__ float  g_pconf[SUMN * CHUNKS];        // per-block partial conf sums
__device__ float  g_pdem[BB * CHUNKS];           // per-block partial demand sums
__device__ float  g_povl[SUMN * CHUNKS];         // per-block partial overlap sums

__device__ __forceinline__ float sigf(float x) {
    return 1.0f / (1.0f + __expf(-x));
}

// block reduce over 256 threads; full sum valid in thread 0
__device__ __forceinline__ float blockReduce256(float v, float* sh) {
    #pragma unroll
    for (int o = 16; o > 0; o >>= 1) v += __shfl_xor_sync(0xffffffffu, v, o);
    if ((threadIdx.x & 31) == 0) sh[threadIdx.x >> 5] = v;
    __syncthreads();
    if (threadIdx.x < 8) {
        v = sh[threadIdx.x];
        #pragma unroll
        for (int o = 4; o > 0; o >>= 1) v += __shfl_xor_sync(0xffu, v, o);
    }
    return v;
}

// conf = sigmoid(max_c psm)  [sigmoid is monotonic];  partial per-image sums; demand for l==0
__global__ void __launch_bounds__(256) k_conf(const float* __restrict__ psm,
                                              const float* __restrict__ req) {
    __shared__ float sh[8];
    int n     = blockIdx.x / CHUNKS;
    int chunk = blockIdx.x % CHUNKS;
    int base  = chunk * 1024 + threadIdx.x * 4;

    const float4 a4 = *(const float4*)(psm + (size_t)n * 2 * HW + base);
    const float4 b4 = *(const float4*)(psm + (size_t)n * 2 * HW + HW + base);
    float4 c;
    c.x = sigf(fmaxf(a4.x, b4.x));
    c.y = sigf(fmaxf(a4.y, b4.y));
    c.z = sigf(fmaxf(a4.z, b4.z));
    c.w = sigf(fmaxf(a4.w, b4.w));

    __half2 h01 = __floats2half2_rn(c.x, c.y);
    __half2 h23 = __floats2half2_rn(c.z, c.w);
    uint2 u;
    u.x = *reinterpret_cast<unsigned int*>(&h01);
    u.y = *reinterpret_cast<unsigned int*>(&h23);
    *reinterpret_cast<uint2*>(g_conf16 + (size_t)n * HW + base) = u;

    float s = (c.x + c.y) + (c.z + c.w);
    float r = blockReduce256(s, sh);
    if (threadIdx.x == 0) g_pconf[n * CHUNKS + chunk] = r;

    if ((n & (LL - 1)) == 0) {   // demand for batch n/8 comes from this image's req_mask
        __syncthreads();         // protect sh reuse
        const float4 d4 = *(const float4*)(req + (size_t)n * HW + base);
        float sd = (d4.x + d4.y) + (d4.z + d4.w);
        float rd = blockReduce256(sd, sh);
        if (threadIdx.x == 0) g_pdem[(n >> 3) * CHUNKS + chunk] = rd;
    }
}

__device__ __forceinline__ float tap16(const __half* __restrict__ img, int y, int x) {
    if ((unsigned)x < WW && (unsigned)y < HH) return __half2float(__ldg(img + y * WW + x));
    return 0.0f;
}

// bilinear warp of conf[b,l] by Aij = norm_affine[b,0,l], dot with Di[b], partial reduce.
// Lane-stride-1 pixel mapping: thread t handles px {chunk*1024 + k*256 + t}.
// Images processed in reverse order so conf lines just written by k_conf hit L2.
__global__ void __launch_bounds__(256) k_warp(const float* __restrict__ na,
                                              const float* __restrict__ req) {
    __shared__ float sh[8];
    int pair  = (SUMN - 1) - blockIdx.x / CHUNKS;   // reverse image order
    int chunk = blockIdx.x % CHUNKS;
    int b = pair >> 3;

    const float* A = na + (size_t)((b * LL + 0) * LL + (pair & 7)) * 6;
    float A00 = A[0], A01 = A[1], A02 = A[2];
    float A10 = A[3], A11 = A[4], A12 = A[5];

    const __half* __restrict__ conf = g_conf16 + (size_t)pair * HW;
    const float*  __restrict__ Di   = req + (size_t)(b * LL) * HW;

    const float step = 2.0f / (WW - 1);
    const float half_span = (WW - 1) * 0.5f;   // 191.5

    float acc = 0.0f;
    int pbase = chunk * 1024 + threadIdx.x;
    #pragma unroll
    for (int k = 0; k < 4; k++) {
        int p = pbase + k * 256;
        int y = p / WW;
        int x = p - y * WW;
        float d = __ldg(Di + p);

        float gx = fmaf((float)x, step, -1.0f);
        float gy = fmaf((float)y, step, -1.0f);
        float sx = fmaf(A00, gx, fmaf(A01, gy, A02));
        float sy = fmaf(A10, gx, fmaf(A11, gy, A12));
        float px = fmaf(sx, half_span, half_span);
        float py = fmaf(sy, half_span, half_span);
        float xf = floorf(px), yf = floorf(py);
        float wx = px - xf, wy = py - yf;
        int xi = (int)xf, yi = (int)yf;

        float v00, v01, v10, v11;
        if ((unsigned)xi <= (WW - 2) && (unsigned)yi <= (HH - 2)) {
            const __half* tp = conf + yi * WW + xi;
            v00 = __half2float(__ldg(tp));
            v01 = __half2float(__ldg(tp + 1));
            v10 = __half2float(__ldg(tp + WW));
            v11 = __half2float(__ldg(tp + WW + 1));
        } else {
            v00 = tap16(conf, yi,     xi);
            v01 = tap16(conf, yi,     xi + 1);
            v10 = tap16(conf, yi + 1, xi);
            v11 = tap16(conf, yi + 1, xi + 1);
        }
        float top = fmaf(wx, v01 - v00, v00);
        float bot = fmaf(wx, v11 - v10, v10);
        acc = fmaf(fmaf(wy, bot - top, top), d, acc);
    }
    float r = blockReduce256(acc, sh);
    if (threadIdx.x == 0) g_povl[pair * CHUNKS + chunk] = r;
}

// MLP head: 8 blocks x 1024 threads; 16 rows per block, 64 threads per row-group
__global__ void __launch_bounds__(1024) k_head(
    const float* __restrict__ na,
    const float* __restrict__ qW1, const float* __restrict__ qb1,
    const float* __restrict__ qW2, const float* __restrict__ qb2,
    const float* __restrict__ kW1, const float* __restrict__ kb1,
    const float* __restrict__ kW2, const float* __restrict__ kb2,
    const float* __restrict__ eW1, const float* __restrict__ eb1,
    const float* __restrict__ eW2, const float* __restrict__ eb2,
    float* __restrict__ out)
{
    __shared__ float s_qW1[512], s_kW1[512];
    __shared__ float s_qb1[64], s_qb2[64], s_kb1[64], s_kb2[64], s_eb1[64], s_eW2[64];
    __shared__ float s_h[16][64];
    __shared__ float s_qk[16][128];
    __shared__ float s_feat[16][8], s_ego[16][8];
    __shared__ float s_scr[16][8];

    int t = threadIdx.x;
    // stage small weights
    for (int i = t; i < 512; i += 1024) { s_qW1[i] = qW1[i]; s_kW1[i] = kW1[i]; }
    if (t < 64) {
        s_qb1[t] = qb1[t]; s_qb2[t] = qb2[t];
        s_kb1[t] = kb1[t]; s_kb2[t] = kb2[t];
        s_eb1[t] = eb1[t]; s_eW2[t] = eW2[t];
    }

    int g    = t >> 6;          // row group 0..15
    int lane = t & 63;
    int row  = blockIdx.x * 16 + g;
    int b = row >> 3, l = row & 7;
    const float invHW = 1.0f / (float)HW;

    // reduce partial sums (144 each) for this row
    float pc = 0.f, po = 0.f, pd = 0.f, pc0 = 0.f;
    for (int i = lane; i < CHUNKS; i += 64) {
        pc  += g_pconf[row * CHUNKS + i];
        po  += g_povl[row * CHUNKS + i];
        pd  += g_pdem[b * CHUNKS + i];
        pc0 += g_pconf[(b * LL) * CHUNKS + i];
    }
    #pragma unroll
    for (int o = 16; o > 0; o >>= 1) {
        pc  += __shfl_xor_sync(0xffffffffu, pc,  o);
        po  += __shfl_xor_sync(0xffffffffu, po,  o);
        pd  += __shfl_xor_sync(0xffffffffu, pd,  o);
        pc0 += __shfl_xor_sync(0xffffffffu, pc0, o);
    }
    if ((lane & 31) == 0) {
        float* scr = &s_scr[g][(lane >> 5) * 4];
        scr[0] = pc; scr[1] = po; scr[2] = pd; scr[3] = pc0;
    }
    __syncthreads();

    if (lane == 0) {
        float sc  = (s_scr[g][0] + s_scr[g][4]) * invHW;
        float so  = (s_scr[g][1] + s_scr[g][5]) * invHW;
        float sd  = (s_scr[g][2] + s_scr[g][6]) * invHW;
        float sc0 = (s_scr[g][3] + s_scr[g][7]) * invHW;
        const float* A  = na + (size_t)((b * LL + 0) * LL + l) * 6;   // Aij
        float dx = A[2], dy = A[5];
        float dist = sqrtf(dx * dx + dy * dy);
        const float* Dl = na + (size_t)((b * LL + l) * LL + l) * 6;   // diag[b,l]
        const float* D0 = na + (size_t)((b * LL + 0) * LL + 0) * 6;   // diag[b,0]
        float yawl = atan2f(Dl[3], Dl[0]);
        float yaw0 = atan2f(D0[3], D0[0]);
        float d = yaw0 - yawl;
        float dyaw = atan2f(sinf(d), cosf(d));
        s_feat[g][0] = sc;   s_feat[g][1] = so;          s_feat[g][2] = dx;
        s_feat[g][3] = dy;   s_feat[g][4] = cosf(dyaw);  s_feat[g][5] = sinf(dyaw);
        s_feat[g][6] = dist; s_feat[g][7] = sd;
        s_ego[g][0] = sc0; s_ego[g][1] = sd;  s_ego[g][2] = 0.0f; s_ego[g][3] = 0.0f;
        s_ego[g][4] = 1.0f; s_ego[g][5] = 0.0f; s_ego[g][6] = 0.0f; s_ego[g][7] = sd;
    }
    __syncthreads();

    // q = mlp2(ego)
    float h = s_qb1[lane];
    #pragma unroll
    for (int i = 0; i < 8; i++) h = fmaf(s_ego[g][i], s_qW1[i * 64 + lane], h);
    s_h[g][lane] = fmaxf(h, 0.0f);
    __syncthreads();
    float qv = s_qb2[lane];
    #pragma unroll 8
    for (int i = 0; i < 64; i++) qv = fmaf(s_h[g][i], __ldg(qW2 + i * 64 + lane), qv);
    s_qk[g][lane] = qv;
    __syncthreads();

    // k = mlp2(feat)
    h = s_kb1[lane];
    #pragma unroll
    for (int i = 0; i < 8; i++) h = fmaf(s_feat[g][i], s_kW1[i * 64 + lane], h);
    s_h[g][lane] = fmaxf(h, 0.0f);
    __syncthreads();
    float kv = s_kb2[lane];
    #pragma unroll 8
    for (int i = 0; i < 64; i++) kv = fmaf(s_h[g][i], __ldg(kW2 + i * 64 + lane), kv);
    s_qk[g][64 + lane] = kv;
    __syncthreads();

    // e = mlp2(concat(q,k)) -> scalar
    float e = s_eb1[lane];
    #pragma unroll 8
    for (int i = 0; i < 128; i++) e = fmaf(s_qk[g][i], __ldg(eW1 + i * 64 + lane), e);
    e = fmaxf(e, 0.0f) * s_eW2[lane];
    #pragma unroll
    for (int o = 16; o > 0; o >>= 1) e += __shfl_xor_sync(0xffffffffu, e, o);
    if ((lane & 31) == 0) s_scr[g][lane >> 5] = e;
    __syncthreads();
    if (lane == 0) {
        float logit = s_scr[g][0] + s_scr[g][1] + eb2[0];
        if (l == 0) logit = NEGV;
        float sg = 1.0f / (1.0f + expf(-logit));
        out[row] = fminf(fmaxf(sg, 0.0f), 1.0f);
    }
}

extern "C" void kernel_launch(void* const* d_in, const int* in_sizes, int n_in,
                              void* d_out, int out_size) {
    const float* psm = (const float*)d_in[0];
    const float* req = (const float*)d_in[1];
    const float* na  = (const float*)d_in[2];
    // d_in[3] = record_len (unused; always full)
    const float* qW1 = (const float*)d_in[4];
    const float* qb1 = (const float*)d_in[5];
    const float* qW2 = (const float*)d_in[6];
    const float* qb2 = (const float*)d_in[7];
    const float* kW1 = (const float*)d_in[8];
    const float* kb1 = (const float*)d_in[9];
    const float* kW2 = (const float*)d_in[10];
    const float* kb2 = (const float*)d_in[11];
    const float* eW1 = (const float*)d_in[12];
    const float* eb1 = (const float*)d_in[13];
    const float* eW2 = (const float*)d_in[14];
    const float* eb2 = (const float*)d_in[15];
    float* out = (float*)d_out;

    k_conf<<<SUMN * CHUNKS, 256>>>(psm, req);
    k_warp<<<SUMN * CHUNKS, 256>>>(na, req);
    k_head<<<SUMN / 16, 1024>>>(na, qW1, qb1, qW2, qb2, kW1, kb1, kW2, kb2,
                                eW1, eb1, eW2, eb2, out);
}